// round 14
// baseline (speedup 1.0000x reference)
#include <cuda_runtime.h>
#include <cuda_fp16.h>
#include <cstdint>

#define BB 2
#define DE 128
#define DO 256
#define TT 16
#define HH 64
#define WW 64
#define HREF 32
#define WREF 32
#define NBLK 16384   // TT * HREF * WREF
#define NCOLS 1024   // HREF * WREF
#define KSEL 32
#define KK 8
#define NCHUNK 32
#define CHUNK 512    // NBLK / NCHUNK
#define LSZ 5        // per-chunk candidate list depth
#define CAPM 64      // per-column candidate cap
#define NEG_INF (-1e30f)

// fused streaming kernel grid layout
#define NPART 256
#define NBLK_IN 2048
#define NBLK_OUT 4096
#define NFUSED (NPART + NBLK_IN + NBLK_OUT)

// attention dynamic smem (float units)
#define SM_K    0        // 32*512 half = 8192 floats
#define SM_Q    8192     // 512
#define SM_P    8704     // 512
#define SM_SEL  9216     // 32
#define SM_CV   9248     // 64
#define SM_CI   9312     // 64
#define SM_CNT  9376     // 1
#define SMEM_ATT_BYTES (9380 * 4 + 128)

// ------------------- device scratch (touched ONLY from device code) --------
__device__ __half g_in_h [(size_t)BB * NBLK * 4 * DE];   // fp16 blockified m_in
__device__ __half g_out_h[(size_t)BB * NBLK * 4 * DO];   // fp16 blockified m_out
__device__ float4 g_pval[(size_t)BB * NCOLS * NCHUNK];
__device__ float  g_pv4 [(size_t)BB * NCOLS * NCHUNK];
__device__ int4   g_pidx[(size_t)BB * NCOLS * NCHUNK];
__device__ int    g_px4 [(size_t)BB * NCOLS * NCHUNK];

// ---------------------------- cp.async helpers -----------------------------
__device__ __forceinline__ void cp16(void* smem_dst, const void* gmem_src) {
    unsigned sa = (unsigned)__cvta_generic_to_shared(smem_dst);
    asm volatile("cp.async.cg.shared.global [%0], [%1], 16;\n" :: "r"(sa), "l"(gmem_src));
}
__device__ __forceinline__ void cp_commit() { asm volatile("cp.async.commit_group;\n"); }
template<int N> __device__ __forceinline__ void cp_wait() {
    asm volatile("cp.async.wait_group %0;\n" :: "n"(N));
}

// ---- blockify body: [B,D,T,H,W] -> fp16 [B, n, pos=i*2+j, D]; half2 stores
template<int D, int NCH>
__device__ __forceinline__ void blockify_body(const float* __restrict__ src,
                                              __half* __restrict__ dst,
                                              int h, int t, int zc,
                                              float (*tile)[65]) {
    const int b  = zc / NCH;
    const int c0 = (zc % NCH) * 128;
    const int tid = threadIdx.x;

    {
        const int w = tid & 63, cr = tid >> 6;
        const float* base = src
            + (size_t)b * D * (TT * HH * WW)
            + (size_t)c0 * (TT * HH * WW)
            + (size_t)t * (HH * WW)
            + (size_t)h * WW;
        for (int c = cr; c < 128; c += 4)
            tile[c][w] = base[(size_t)c * (TT * HH * WW) + w];
    }
    __syncthreads();

    const int hb = h >> 1, ii = h & 1;
    const int cp = tid & 63;             // channel pair: c = 2cp, 2cp+1
    const int mg = tid >> 6;             // 0..3
    const size_t blk_base = (size_t)b * NBLK + (size_t)t * (HREF * WREF) + (size_t)hb * WREF;
#pragma unroll
    for (int m = mg; m < 64; m += 4) {
        const int wb = m >> 1, jj = m & 1;
        const size_t o = ((blk_base + wb) * 4 + (ii * 2 + jj)) * (size_t)D + c0 + 2 * cp;
        *(__half2*)(dst + o) = __floats2half2_rn(tile[2 * cp][m], tile[2 * cp + 1][m]);
    }
}

// ---- partial body: per (column, chunk) thread; register top-5 -------------
__device__ __forceinline__ void partial_body(const float* __restrict__ qk,
                                             int jBlk, int chunk, int b) {
    const int tid = threadIdx.x;
    const int j = jBlk * 256 + tid;
    const float* col = qk + (size_t)b * NBLK * NCOLS + (size_t)chunk * CHUNK * NCOLS + j;

    float w[LSZ];
    int   x[LSZ];
#pragma unroll
    for (int e = 0; e < LSZ; e++) { w[e] = NEG_INF; x[e] = 0x7fffffff; }
    const int rbase = chunk * CHUNK;

    for (int r0 = 0; r0 < CHUNK; r0 += 16) {
        float vv[16];
#pragma unroll
        for (int u = 0; u < 16; u++) vv[u] = col[(size_t)(r0 + u) * NCOLS];
#pragma unroll
        for (int u = 0; u < 16; u++) {
            const float v = vv[u];
            if (v > w[LSZ - 1]) {              // strict > + asc scan = jax ties
                const int myi = rbase + r0 + u;
                bool bprev = true;
#pragma unroll
                for (int e = LSZ - 1; e >= 1; e--) {
                    const bool b1 = v > w[e - 1];
                    w[e] = b1 ? w[e - 1] : (bprev ? v   : w[e]);
                    x[e] = b1 ? x[e - 1] : (bprev ? myi : x[e]);
                    bprev = b1;
                }
                if (bprev) { w[0] = v; x[0] = myi; }
            }
        }
    }
    const size_t o = (size_t)(b * NCOLS + j) * NCHUNK + chunk;
    g_pval[o] = make_float4(w[0], w[1], w[2], w[3]);
    g_pv4 [o] = w[4];
    g_pidx[o] = make_int4(x[0], x[1], x[2], x[3]);
    g_px4 [o] = x[4];
}

// ---- fused streaming kernel ------------------------------------------------
__global__ void fused_stream_k(const float* __restrict__ m_in,
                               const float* __restrict__ m_out,
                               const float* __restrict__ qk) {
    __shared__ float tile[128][65];
    const int bid = blockIdx.x;
    if (bid < NPART) {
        partial_body(qk, bid & 3, (bid >> 2) & 31, bid >> 7);
    } else if (bid < NPART + NBLK_IN) {
        const int id = bid - NPART;
        blockify_body<DE, 1>(m_in, g_in_h, id & 63, (id >> 6) & 15, id >> 10, tile);
    } else {
        const int id = bid - NPART - NBLK_IN;
        blockify_body<DO, 2>(m_out, g_out_h, id & 63, (id >> 6) & 15, id >> 10, tile);
    }
}

// ---- warp sort / merge (desc, value-only) ---------------------------------
__device__ __forceinline__ float wsort_desc(float c) {
    const int lane = threadIdx.x & 31;
#pragma unroll
    for (int k = 2; k <= 32; k <<= 1)
#pragma unroll
        for (int d = k >> 1; d; d >>= 1) {
            const float o = __shfl_xor_sync(0xffffffffu, c, d);
            const bool keepmax = (((lane & d) == 0) == ((lane & k) == 0));
            c = keepmax ? fmaxf(c, o) : fminf(c, o);
        }
    return c;
}
__device__ __forceinline__ float wmerge_desc(float a, float bfull) {
    const int lane = threadIdx.x & 31;
    const float br = __shfl_sync(0xffffffffu, bfull, 31 - lane);
    float c = fmaxf(a, br);
#pragma unroll
    for (int d = 16; d >= 1; d >>= 1) {
        const float o = __shfl_xor_sync(0xffffffffu, c, d);
        c = ((lane & d) == 0) ? fmaxf(c, o) : fminf(c, o);
    }
    return c;
}
__device__ __forceinline__ int wsort_int_asc(int x) {
    const int lane = threadIdx.x & 31;
#pragma unroll
    for (int k = 2; k <= 32; k <<= 1)
#pragma unroll
        for (int d = k >> 1; d; d >>= 1) {
            const int o = __shfl_xor_sync(0xffffffffu, x, d);
            const bool keepmin = (((lane & d) == 0) == ((lane & k) == 0));
            x = keepmin ? min(x, o) : max(x, o);
        }
    return x;
}
__device__ __forceinline__ bool beats(float av, int ai, float bv, int bi) {
    return (av > bv) || (av == bv && ai < bi);
}

// ---- attention with integrated per-column merge ---------------------------
// grid (BB*NCOLS), block 256, dynamic smem ~37.5 KB
__global__ void __launch_bounds__(256) attention_k(
        const float* __restrict__ q_in, const float* __restrict__ qk,
        float* __restrict__ out,
        float* __restrict__ out_idx, float* __restrict__ out_val) {
    extern __shared__ float sm[];
    __half* kbuf  = (__half*)(sm + SM_K);   // [32][512] halves (32 KB)
    float*  q_s   = sm + SM_Q;              // [4][128]
    float*  p_s   = sm + SM_P;              // [4][128]
    int*    sel   = (int*)(sm + SM_SEL);
    float*  cv    = sm + SM_CV;             // [CAPM]
    int*    ci    = (int*)(sm + SM_CI);     // [CAPM]
    int*    cntp  = (int*)(sm + SM_CNT);

    const int tid = threadIdx.x;
    const int b = blockIdx.x >> 10;
    const int colq = blockIdx.x & 1023;
    const int hr = colq >> 5, wr = colq & 31;
    const int cb = b * NCOLS + colq;

    // ---- warp 0: merge + finalize this column's top-32 --------------------
    if (tid < 32) {
        const int lane = tid;
        const size_t po = (size_t)cb * NCHUNK + lane;
        const float4 pv = g_pval[po];
        const float  v4 = g_pv4[po];
        const int4   pi = g_pidx[po];
        const int    i4 = g_px4[po];

        float s = wsort_desc(pv.x);
        s = wmerge_desc(s, wsort_desc(pv.y));
        s = wmerge_desc(s, wsort_desc(pv.z));
        s = wmerge_desc(s, wsort_desc(pv.w));
        s = wmerge_desc(s, wsort_desc(v4));
        const float cut = __shfl_sync(0xffffffffu, s, 31);

        if (lane == 0) *cntp = 0;
        __syncwarp();

        const bool flagged = (v4 >= cut);
        if (!flagged) {
            const float fv[LSZ] = {pv.x, pv.y, pv.z, pv.w, v4};
            const int   fi[LSZ] = {pi.x, pi.y, pi.z, pi.w, i4};
#pragma unroll
            for (int e = 0; e < LSZ; e++)
                if (fv[e] >= cut) {
                    const int pos = atomicAdd(cntp, 1);
                    if (pos < CAPM) { cv[pos] = fv[e]; ci[pos] = fi[e]; }
                }
        }
        unsigned mask = __ballot_sync(0xffffffffu, flagged);
        while (mask) {                     // rare: rescan flagged chunks, MLP=16
            const int cc = __ffs(mask) - 1; mask &= mask - 1;
            const float* colp = qk + (size_t)b * NBLK * NCOLS + (size_t)(cc * CHUNK) * NCOLS + colq;
            float vv[16];
#pragma unroll
            for (int u = 0; u < 16; u++)
                vv[u] = __ldg(colp + (size_t)(lane + u * 32) * NCOLS);
#pragma unroll
            for (int u = 0; u < 16; u++) {
                if (vv[u] >= cut) {
                    const int pos = atomicAdd(cntp, 1);
                    if (pos < CAPM) { cv[pos] = vv[u]; ci[pos] = cc * CHUNK + lane + u * 32; }
                }
            }
        }
        __syncwarp();
        const int n = min(*cntp, CAPM);
        for (int t = lane; t < CAPM; t += 32)
            if (t >= n) { cv[t] = NEG_INF; ci[t] = 0x7fffffff; }
        __syncwarp();

        // bitonic sort CAPM=64, desc by (v desc, idx asc)
        for (int k = 2; k <= CAPM; k <<= 1) {
            for (int jj = k >> 1; jj > 0; jj >>= 1) {
#pragma unroll
                for (int t = lane; t < CAPM; t += 32) {
                    const int ixj = t ^ jj;
                    if (ixj > t) {
                        float av = cv[t], bv = cv[ixj];
                        int   ai = ci[t], bi = ci[ixj];
                        const bool desc = ((t & k) == 0);
                        const bool sw = desc ? beats(bv, bi, av, ai) : beats(av, ai, bv, bi);
                        if (sw) { cv[t] = bv; cv[ixj] = av; ci[t] = bi; ci[ixj] = ai; }
                    }
                }
                __syncwarp();
            }
        }

        if (lane < KK) {
            out_val[cb * KK + lane] = cv[lane];
            out_idx[cb * KK + lane] = (float)ci[lane];
        }
        sel[lane] = wsort_int_asc(ci[lane]);   // ascending top-32 indices
    }
    __syncthreads();

    // ---- issue ALL 32 K-block cp.asyncs (32 KB, one commit group) ---------
    const size_t gbase = (size_t)b * NBLK;
#pragma unroll
    for (int i = 0; i < 8; i++) {
        const int f4 = i * 256 + tid;
        const int slot = f4 >> 6, off = f4 & 63;
        cp16(kbuf + (size_t)f4 * 8,
             (const uint4*)g_in_h + (gbase + sel[slot]) * 64 + off);
    }
    cp_commit();

    // q load + pre-scale (overlaps K transfer)
    {
        const int c = tid & 127, ii = tid >> 7;
        const size_t qoff = ((size_t)(b * DE + c) * HH + (2 * hr + ii)) * WW + 2 * wr;
        const float2 qv = *(const float2*)(q_in + qoff);
        const float sc = 0.08838834764831845f;     // 1/sqrt(128)
        q_s[(ii * 2 + 0) * 128 + c] = qv.x * sc;
        q_s[(ii * 2 + 1) * 128 + c] = qv.y * sc;
    }

    // V prefetch (depth 8) issued BEFORE QK
    __half vr[8][4];
#pragma unroll
    for (int s = 0; s < 8; s++) {
        const __half* src = g_out_h + (gbase + sel[s]) * 1024 + tid;
#pragma unroll
        for (int pos = 0; pos < 4; pos++) vr[s][pos] = __ldg(src + pos * 256);
    }

    cp_wait<0>();
    __syncthreads();

    // QK: sync-free; q fp32 in registers, K half2 from smem
    const int grp = tid >> 4, sub = tid & 15;
    const int ql = grp >> 2, pl = grp & 3;
    float qr[8];
#pragma unroll
    for (int k = 0; k < 4; k++) {
        qr[2 * k]     = q_s[ql * 128 + 2 * (sub + 16 * k)];
        qr[2 * k + 1] = q_s[ql * 128 + 2 * (sub + 16 * k) + 1];
    }
#pragma unroll 4
    for (int s = 0; s < KSEL; s++) {
        const __half2* kv = (const __half2*)kbuf + s * 256 + pl * 64;
        float part = 0.f;
#pragma unroll
        for (int k = 0; k < 4; k++) {
            const float2 kf = __half22float2(kv[sub + 16 * k]);
            part += qr[2 * k] * kf.x + qr[2 * k + 1] * kf.y;
        }
        part += __shfl_xor_sync(0xffffffffu, part, 8);
        part += __shfl_xor_sync(0xffffffffu, part, 4);
        part += __shfl_xor_sync(0xffffffffu, part, 2);
        part += __shfl_xor_sync(0xffffffffu, part, 1);
        if (sub == 0) p_s[ql * 128 + s * 4 + pl] = part;
    }
    __syncthreads();

    // softmax over 128 keys; one warp per query
    {
        const int w = tid >> 5, lane = tid & 31;
        if (w < 4) {
            float x0 = p_s[w * 128 + lane],      x1 = p_s[w * 128 + lane + 32];
            float x2 = p_s[w * 128 + lane + 64], x3 = p_s[w * 128 + lane + 96];
            float m = fmaxf(fmaxf(x0, x1), fmaxf(x2, x3));
#pragma unroll
            for (int o = 16; o; o >>= 1) m = fmaxf(m, __shfl_xor_sync(0xffffffffu, m, o));
            float e0 = __expf(x0 - m), e1 = __expf(x1 - m);
            float e2 = __expf(x2 - m), e3 = __expf(x3 - m);
            float ssum = e0 + e1 + e2 + e3;
#pragma unroll
            for (int o = 16; o; o >>= 1) ssum += __shfl_xor_sync(0xffffffffu, ssum, o);
            const float inv = __fdividef(1.f, ssum);
            p_s[w * 128 + lane]      = e0 * inv; p_s[w * 128 + lane + 32] = e1 * inv;
            p_s[w * 128 + lane + 64] = e2 * inv; p_s[w * 128 + lane + 96] = e3 * inv;
        }
    }
    __syncthreads();

    // PV: fp16 register-direct LDG pipeline, depth 8, zero syncs
    float a0 = 0.f, a1 = 0.f, a2 = 0.f, a3 = 0.f;
#pragma unroll 8
    for (int s = 0; s < KSEL; s++) {
        const int rs = s & 7;
        const float4 p0 = *(const float4*)(p_s + 0 * 128 + s * 4);
        const float4 p1 = *(const float4*)(p_s + 1 * 128 + s * 4);
        const float4 p2 = *(const float4*)(p_s + 2 * 128 + s * 4);
        const float4 p3 = *(const float4*)(p_s + 3 * 128 + s * 4);
        const float v0 = __half2float(vr[rs][0]);
        const float v1 = __half2float(vr[rs][1]);
        const float v2 = __half2float(vr[rs][2]);
        const float v3 = __half2float(vr[rs][3]);
        a0 += v0 * p0.x + v1 * p0.y + v2 * p0.z + v3 * p0.w;
        a1 += v0 * p1.x + v1 * p1.y + v2 * p1.z + v3 * p1.w;
        a2 += v0 * p2.x + v1 * p2.y + v2 * p2.z + v3 * p2.w;
        a3 += v0 * p3.x + v1 * p3.y + v2 * p3.z + v3 * p3.w;
        if (s + 8 < KSEL) {
            const __half* src = g_out_h + (gbase + sel[s + 8]) * 1024 + tid;
#pragma unroll
            for (int pos = 0; pos < 4; pos++) vr[rs][pos] = __ldg(src + pos * 256);
        }
    }

    const size_t ob = ((size_t)(b * DO + tid) * HH + 2 * hr) * WW + 2 * wr;
    *(float2*)(out + ob)      = make_float2(a0, a1);
    *(float2*)(out + ob + WW) = make_float2(a2, a3);
}

// ---------------------------------------------------------------------------
extern "C" void kernel_launch(void* const* d_in, const int* in_sizes, int n_in,
                              void* d_out, int out_size) {
    const float* m_in   = (const float*)d_in[0];
    const float* m_out  = (const float*)d_in[1];
    const float* q_in   = (const float*)d_in[2];
    const float* qk_ref = (const float*)d_in[3];

    float* out_mem = (float*)d_out;
    float* out_idx = out_mem + (size_t)BB * DO * HH * WW;
    float* out_val = out_idx + (size_t)BB * NCOLS * KK;

    // fused: topk partial + blockify m_in + blockify m_out (one launch)
    fused_stream_k<<<NFUSED, 256>>>(m_in, m_out, qk_ref);
    // attention with per-column merge fused in (writes all three outputs)
    cudaFuncSetAttribute(attention_k, cudaFuncAttributeMaxDynamicSharedMemorySize, SMEM_ATT_BYTES);
    attention_k<<<BB * NCOLS, 256, SMEM_ATT_BYTES>>>(q_in, qk_ref, out_mem, out_idx, out_val);
}

// round 15
// speedup vs baseline: 1.0512x; 1.0512x over previous
#include <cuda_runtime.h>
#include <cuda_fp16.h>
#include <cstdint>

#define BB 2
#define DE 128
#define DO 256
#define TT 16
#define HH 64
#define WW 64
#define HREF 32
#define WREF 32
#define NBLK 16384   // TT * HREF * WREF
#define NCOLS 1024   // HREF * WREF
#define KSEL 32
#define KK 8
#define NCHUNK 32
#define CHUNK 512    // NBLK / NCHUNK
#define LSZ 5        // per-chunk candidate list depth
#define CAPM 64      // per-column candidate cap in merge
#define NEG_INF (-1e30f)

// fused streaming kernel grid layout
#define NPART 256
#define NBLK_IN 2048
#define NBLK_OUT 4096
#define NFUSED (NPART + NBLK_IN + NBLK_OUT)

// attention dynamic smem (float units): kbuf 32*512 half = 8192 f | q 512 | p 512 | sel 32
#define SM_K    0
#define SM_Q    8192
#define SM_P    8704
#define SM_SEL  9216
#define SMEM_ATT_BYTES (9248 * 4 + 128)

// ------------------- device scratch (touched ONLY from device code) --------
__device__ __half g_in_h [(size_t)BB * NBLK * 4 * DE];   // fp16 blockified m_in
__device__ __half g_out_h[(size_t)BB * NBLK * 4 * DO];   // fp16 blockified m_out
__device__ float4 g_pval[(size_t)BB * NCOLS * NCHUNK];
__device__ float  g_pv4 [(size_t)BB * NCOLS * NCHUNK];
__device__ int4   g_pidx[(size_t)BB * NCOLS * NCHUNK];
__device__ int    g_px4 [(size_t)BB * NCOLS * NCHUNK];
__device__ int    g_sel [(size_t)BB * NCOLS * KSEL];     // asc-sorted top-32

// ---------------------------- cp.async helpers -----------------------------
__device__ __forceinline__ void cp16(void* smem_dst, const void* gmem_src) {
    unsigned sa = (unsigned)__cvta_generic_to_shared(smem_dst);
    asm volatile("cp.async.cg.shared.global [%0], [%1], 16;\n" :: "r"(sa), "l"(gmem_src));
}
__device__ __forceinline__ void cp_commit() { asm volatile("cp.async.commit_group;\n"); }
template<int N> __device__ __forceinline__ void cp_wait() {
    asm volatile("cp.async.wait_group %0;\n" :: "n"(N));
}

// ---- blockify body: [B,D,T,H,W] -> fp16 [B, n, pos=i*2+j, D]; half2 stores
template<int D, int NCH>
__device__ __forceinline__ void blockify_body(const float* __restrict__ src,
                                              __half* __restrict__ dst,
                                              int h, int t, int zc,
                                              float (*tile)[65]) {
    const int b  = zc / NCH;
    const int c0 = (zc % NCH) * 128;
    const int tid = threadIdx.x;

    {
        const int w = tid & 63, cr = tid >> 6;
        const float* base = src
            + (size_t)b * D * (TT * HH * WW)
            + (size_t)c0 * (TT * HH * WW)
            + (size_t)t * (HH * WW)
            + (size_t)h * WW;
        for (int c = cr; c < 128; c += 4)
            tile[c][w] = base[(size_t)c * (TT * HH * WW) + w];
    }
    __syncthreads();

    const int hb = h >> 1, ii = h & 1;
    const int cp = tid & 63;             // channel pair: c = 2cp, 2cp+1
    const int mg = tid >> 6;             // 0..3
    const size_t blk_base = (size_t)b * NBLK + (size_t)t * (HREF * WREF) + (size_t)hb * WREF;
#pragma unroll
    for (int m = mg; m < 64; m += 4) {
        const int wb = m >> 1, jj = m & 1;
        const size_t o = ((blk_base + wb) * 4 + (ii * 2 + jj)) * (size_t)D + c0 + 2 * cp;
        *(__half2*)(dst + o) = __floats2half2_rn(tile[2 * cp][m], tile[2 * cp + 1][m]);
    }
}

// ---- partial body: per (column, chunk) thread; register top-5 -------------
__device__ __forceinline__ void partial_body(const float* __restrict__ qk,
                                             int jBlk, int chunk, int b) {
    const int tid = threadIdx.x;
    const int j = jBlk * 256 + tid;
    const float* col = qk + (size_t)b * NBLK * NCOLS + (size_t)chunk * CHUNK * NCOLS + j;

    float w[LSZ];
    int   x[LSZ];
#pragma unroll
    for (int e = 0; e < LSZ; e++) { w[e] = NEG_INF; x[e] = 0x7fffffff; }
    const int rbase = chunk * CHUNK;

    for (int r0 = 0; r0 < CHUNK; r0 += 16) {
        float vv[16];
#pragma unroll
        for (int u = 0; u < 16; u++) vv[u] = col[(size_t)(r0 + u) * NCOLS];
#pragma unroll
        for (int u = 0; u < 16; u++) {
            const float v = vv[u];
            if (v > w[LSZ - 1]) {              // strict > + asc scan = jax ties
                const int myi = rbase + r0 + u;
                bool bprev = true;
#pragma unroll
                for (int e = LSZ - 1; e >= 1; e--) {
                    const bool b1 = v > w[e - 1];
                    w[e] = b1 ? w[e - 1] : (bprev ? v   : w[e]);
                    x[e] = b1 ? x[e - 1] : (bprev ? myi : x[e]);
                    bprev = b1;
                }
                if (bprev) { w[0] = v; x[0] = myi; }
            }
        }
    }
    const size_t o = (size_t)(b * NCOLS + j) * NCHUNK + chunk;
    g_pval[o] = make_float4(w[0], w[1], w[2], w[3]);
    g_pv4 [o] = w[4];
    g_pidx[o] = make_int4(x[0], x[1], x[2], x[3]);
    g_px4 [o] = x[4];
}

// ---- fused streaming kernel ------------------------------------------------
__global__ void fused_stream_k(const float* __restrict__ m_in,
                               const float* __restrict__ m_out,
                               const float* __restrict__ qk) {
    __shared__ float tile[128][65];
    const int bid = blockIdx.x;
    if (bid < NPART) {
        partial_body(qk, bid & 3, (bid >> 2) & 31, bid >> 7);
    } else if (bid < NPART + NBLK_IN) {
        const int id = bid - NPART;
        blockify_body<DE, 1>(m_in, g_in_h, id & 63, (id >> 6) & 15, id >> 10, tile);
    } else {
        const int id = bid - NPART - NBLK_IN;
        blockify_body<DO, 2>(m_out, g_out_h, id & 63, (id >> 6) & 15, id >> 10, tile);
    }
}

// ---- warp sort / merge (desc, value-only) ---------------------------------
__device__ __forceinline__ float wsort_desc(float c) {
    const int lane = threadIdx.x & 31;
#pragma unroll
    for (int k = 2; k <= 32; k <<= 1)
#pragma unroll
        for (int d = k >> 1; d; d >>= 1) {
            const float o = __shfl_xor_sync(0xffffffffu, c, d);
            const bool keepmax = (((lane & d) == 0) == ((lane & k) == 0));
            c = keepmax ? fmaxf(c, o) : fminf(c, o);
        }
    return c;
}
__device__ __forceinline__ float wmerge_desc(float a, float bfull) {
    const int lane = threadIdx.x & 31;
    const float br = __shfl_sync(0xffffffffu, bfull, 31 - lane);
    float c = fmaxf(a, br);
#pragma unroll
    for (int d = 16; d >= 1; d >>= 1) {
        const float o = __shfl_xor_sync(0xffffffffu, c, d);
        c = ((lane & d) == 0) ? fmaxf(c, o) : fminf(c, o);
    }
    return c;
}
__device__ __forceinline__ int wsort_int_asc(int x) {
    const int lane = threadIdx.x & 31;
#pragma unroll
    for (int k = 2; k <= 32; k <<= 1)
#pragma unroll
        for (int d = k >> 1; d; d >>= 1) {
            const int o = __shfl_xor_sync(0xffffffffu, x, d);
            const bool keepmin = (((lane & d) == 0) == ((lane & k) == 0));
            x = keepmin ? min(x, o) : max(x, o);
        }
    return x;
}
__device__ __forceinline__ bool beats(float av, int ai, float bv, int bi) {
    return (av > bv) || (av == bv && ai < bi);
}

// ---- merge + finalize: exact top-32 per column ----------------------------
// grid (NCOLS/8, BB), block 256 (8 warps, 1 column each)
__global__ void topk_merge_k(const float* __restrict__ qk,
                             float* __restrict__ out_idx, float* __restrict__ out_val) {
    __shared__ float cand_v[8][CAPM];
    __shared__ int   cand_i[8][CAPM];
    __shared__ int   cnt[8];
    const int tid = threadIdx.x, lane = tid & 31, w = tid >> 5;
    const int col = blockIdx.x * 8 + w, b = blockIdx.y;
    const int cb = b * NCOLS + col;

    const size_t po = (size_t)cb * NCHUNK + lane;
    const float4 pv = g_pval[po];
    const float  v4 = g_pv4[po];
    const int4   pi = g_pidx[po];
    const int    i4 = g_px4[po];

    float s = wsort_desc(pv.x);
    s = wmerge_desc(s, wsort_desc(pv.y));
    s = wmerge_desc(s, wsort_desc(pv.z));
    s = wmerge_desc(s, wsort_desc(pv.w));
    s = wmerge_desc(s, wsort_desc(v4));
    const float cut = __shfl_sync(0xffffffffu, s, 31);

    if (lane == 0) cnt[w] = 0;
    __syncwarp();

    const bool flagged = (v4 >= cut);
    if (!flagged) {
        const float fv[LSZ] = {pv.x, pv.y, pv.z, pv.w, v4};
        const int   fi[LSZ] = {pi.x, pi.y, pi.z, pi.w, i4};
#pragma unroll
        for (int e = 0; e < LSZ; e++)
            if (fv[e] >= cut) {
                const int pos = atomicAdd(&cnt[w], 1);
                if (pos < CAPM) { cand_v[w][pos] = fv[e]; cand_i[w][pos] = fi[e]; }
            }
    }
    unsigned mask = __ballot_sync(0xffffffffu, flagged);
    while (mask) {                        // rare: rescan flagged chunks, MLP=16
        const int cc = __ffs(mask) - 1; mask &= mask - 1;
        const float* colp = qk + (size_t)b * NBLK * NCOLS + (size_t)(cc * CHUNK) * NCOLS + col;
        float vv[16];
#pragma unroll
        for (int u = 0; u < 16; u++)
            vv[u] = __ldg(colp + (size_t)(lane + u * 32) * NCOLS);
#pragma unroll
        for (int u = 0; u < 16; u++) {
            if (vv[u] >= cut) {
                const int pos = atomicAdd(&cnt[w], 1);
                if (pos < CAPM) { cand_v[w][pos] = vv[u]; cand_i[w][pos] = cc * CHUNK + lane + u * 32; }
            }
        }
    }
    __syncwarp();
    const int n = min(cnt[w], CAPM);
    for (int t = lane; t < CAPM; t += 32)
        if (t >= n) { cand_v[w][t] = NEG_INF; cand_i[w][t] = 0x7fffffff; }
    __syncwarp();

    for (int k = 2; k <= CAPM; k <<= 1) {
        for (int jj = k >> 1; jj > 0; jj >>= 1) {
#pragma unroll
            for (int t = lane; t < CAPM; t += 32) {
                const int ixj = t ^ jj;
                if (ixj > t) {
                    float av = cand_v[w][t], bv = cand_v[w][ixj];
                    int   ai = cand_i[w][t], bi = cand_i[w][ixj];
                    const bool desc = ((t & k) == 0);
                    const bool sw = desc ? beats(bv, bi, av, ai) : beats(av, ai, bv, bi);
                    if (sw) { cand_v[w][t] = bv; cand_v[w][ixj] = av;
                              cand_i[w][t] = bi; cand_i[w][ixj] = ai; }
                }
            }
            __syncwarp();
        }
    }

    if (lane < KK) {
        out_val[cb * KK + lane] = cand_v[w][lane];
        out_idx[cb * KK + lane] = (float)cand_i[w][lane];
    }
    const int asc = wsort_int_asc(cand_i[w][lane]);
    g_sel[(size_t)cb * KSEL + lane] = asc;
}

// ---- attention: fp16 K resident in smem; fp16 V depth-8 register ring -----
// grid (BB*NCOLS), block 256, dynamic smem ~37 KB
__global__ void __launch_bounds__(256) attention_k(
        const float* __restrict__ q_in, float* __restrict__ out) {
    extern __shared__ float sm[];
    __half* kbuf = (__half*)(sm + SM_K);   // [32][512] halves (32 KB)
    float*  q_s  = sm + SM_Q;              // [4][128]
    float*  p_s  = sm + SM_P;              // [4][128]
    int*    sel  = (int*)(sm + SM_SEL);

    const int tid = threadIdx.x;
    const int b = blockIdx.x >> 10;
    const int colq = blockIdx.x & 1023;
    const int hr = colq >> 5, wr = colq & 31;
    const int cb = b * NCOLS + colq;

    if (tid < KSEL) sel[tid] = g_sel[(size_t)cb * KSEL + tid];
    __syncthreads();

    // issue ALL 32 K-block cp.asyncs (32 KB, one commit group)
    const size_t gbase = (size_t)b * NBLK;
#pragma unroll
    for (int i = 0; i < 8; i++) {
        const int f4 = i * 256 + tid;
        const int slot = f4 >> 6, off = f4 & 63;
        cp16(kbuf + (size_t)f4 * 8,
             (const uint4*)g_in_h + (gbase + sel[slot]) * 64 + off);
    }
    cp_commit();

    // q load + pre-scale (overlaps K transfer)
    {
        const int c = tid & 127, ii = tid >> 7;
        const size_t qoff = ((size_t)(b * DE + c) * HH + (2 * hr + ii)) * WW + 2 * wr;
        const float2 qv = *(const float2*)(q_in + qoff);
        const float sc = 0.08838834764831845f;     // 1/sqrt(128)
        q_s[(ii * 2 + 0) * 128 + c] = qv.x * sc;
        q_s[(ii * 2 + 1) * 128 + c] = qv.y * sc;
    }

    // V prefetch (depth 8) issued BEFORE QK
    __half vr[8][4];
#pragma unroll
    for (int s = 0; s < 8; s++) {
        const __half* src = g_out_h + (gbase + sel[s]) * 1024 + tid;
#pragma unroll
        for (int pos = 0; pos < 4; pos++) vr[s][pos] = __ldg(src + pos * 256);
    }

    cp_wait<0>();
    __syncthreads();

    // QK: sync-free; q fp32 in registers, K half2 from smem
    const int grp = tid >> 4, sub = tid & 15;
    const int ql = grp >> 2, pl = grp & 3;
    float qr[8];
#pragma unroll
    for (int k = 0; k < 4; k++) {
        qr[2 * k]     = q_s[ql * 128 + 2 * (sub + 16 * k)];
        qr[2 * k + 1] = q_s[ql * 128 + 2 * (sub + 16 * k) + 1];
    }
#pragma unroll 4
    for (int s = 0; s < KSEL; s++) {
        const __half2* kv = (const __half2*)kbuf + s * 256 + pl * 64;
        float part = 0.f;
#pragma unroll
        for (int k = 0; k < 4; k++) {
            const float2 kf = __half22float2(kv[sub + 16 * k]);
            part += qr[2 * k] * kf.x + qr[2 * k + 1] * kf.y;
        }
        part += __shfl_xor_sync(0xffffffffu, part, 8);
        part += __shfl_xor_sync(0xffffffffu, part, 4);
        part += __shfl_xor_sync(0xffffffffu, part, 2);
        part += __shfl_xor_sync(0xffffffffu, part, 1);
        if (sub == 0) p_s[ql * 128 + s * 4 + pl] = part;
    }
    __syncthreads();

    // softmax over 128 keys; one warp per query
    {
        const int w = tid >> 5, lane = tid & 31;
        if (w < 4) {
            float x0 = p_s[w * 128 + lane],      x1 = p_s[w * 128 + lane + 32];
            float x2 = p_s[w * 128 + lane + 64], x3 = p_s[w * 128 + lane + 96];
            float m = fmaxf(fmaxf(x0, x1), fmaxf(x2, x3));
#pragma unroll
            for (int o = 16; o; o >>= 1) m = fmaxf(m, __shfl_xor_sync(0xffffffffu, m, o));
            float e0 = __expf(x0 - m), e1 = __expf(x1 - m);
            float e2 = __expf(x2 - m), e3 = __expf(x3 - m);
            float ssum = e0 + e1 + e2 + e3;
#pragma unroll
            for (int o = 16; o; o >>= 1) ssum += __shfl_xor_sync(0xffffffffu, ssum, o);
            const float inv = __fdividef(1.f, ssum);
            p_s[w * 128 + lane]      = e0 * inv; p_s[w * 128 + lane + 32] = e1 * inv;
            p_s[w * 128 + lane + 64] = e2 * inv; p_s[w * 128 + lane + 96] = e3 * inv;
        }
    }
    __syncthreads();

    // PV: fp16 register-direct LDG pipeline, depth 8, zero syncs
    float a0 = 0.f, a1 = 0.f, a2 = 0.f, a3 = 0.f;
#pragma unroll 8
    for (int s = 0; s < KSEL; s++) {
        const int rs = s & 7;
        const float4 p0 = *(const float4*)(p_s + 0 * 128 + s * 4);
        const float4 p1 = *(const float4*)(p_s + 1 * 128 + s * 4);
        const float4 p2 = *(const float4*)(p_s + 2 * 128 + s * 4);
        const float4 p3 = *(const float4*)(p_s + 3 * 128 + s * 4);
        const float v0 = __half2float(vr[rs][0]);
        const float v1 = __half2float(vr[rs][1]);
        const float v2 = __half2float(vr[rs][2]);
        const float v3 = __half2float(vr[rs][3]);
        a0 += v0 * p0.x + v1 * p0.y + v2 * p0.z + v3 * p0.w;
        a1 += v0 * p1.x + v1 * p1.y + v2 * p1.z + v3 * p1.w;
        a2 += v0 * p2.x + v1 * p2.y + v2 * p2.z + v3 * p2.w;
        a3 += v0 * p3.x + v1 * p3.y + v2 * p3.z + v3 * p3.w;
        if (s + 8 < KSEL) {
            const __half* src = g_out_h + (gbase + sel[s + 8]) * 1024 + tid;
#pragma unroll
            for (int pos = 0; pos < 4; pos++) vr[rs][pos] = __ldg(src + pos * 256);
        }
    }

    const size_t ob = ((size_t)(b * DO + tid) * HH + 2 * hr) * WW + 2 * wr;
    *(float2*)(out + ob)      = make_float2(a0, a1);
    *(float2*)(out + ob + WW) = make_float2(a2, a3);
}

// ---------------------------------------------------------------------------
extern "C" void kernel_launch(void* const* d_in, const int* in_sizes, int n_in,
                              void* d_out, int out_size) {
    const float* m_in   = (const float*)d_in[0];
    const float* m_out  = (const float*)d_in[1];
    const float* q_in   = (const float*)d_in[2];
    const float* qk_ref = (const float*)d_in[3];

    float* out_mem = (float*)d_out;
    float* out_idx = out_mem + (size_t)BB * DO * HH * WW;
    float* out_val = out_idx + (size_t)BB * NCOLS * KK;

    // fused: topk partial + blockify m_in + blockify m_out (one launch)
    fused_stream_k<<<NFUSED, 256>>>(m_in, m_out, qk_ref);
    // merge + finalize selection (standalone: overlaps across 8 warps/CTA)
    {
        dim3 gm(NCOLS / 8, BB);
        topk_merge_k<<<gm, 256>>>(qk_ref, out_idx, out_val);
    }
    // attention
    cudaFuncSetAttribute(attention_k, cudaFuncAttributeMaxDynamicSharedMemorySize, SMEM_ATT_BYTES);
    attention_k<<<BB * NCOLS, 256, SMEM_ATT_BYTES>>>(q_in, out_mem);
}

// round 16
// speedup vs baseline: 1.1223x; 1.0676x over previous
#include <cuda_runtime.h>
#include <cuda_fp16.h>
#include <cstdint>

#define BB 2
#define DE 128
#define DO 256
#define TT 16
#define HH 64
#define WW 64
#define HREF 32
#define WREF 32
#define NBLK 16384   // TT * HREF * WREF
#define NCOLS 1024   // HREF * WREF
#define KSEL 32
#define KK 8
#define NCHUNK 32
#define CHUNK 512    // NBLK / NCHUNK
#define LSZ 5        // per-chunk candidate list depth
#define CAPM 64      // per-column candidate cap in merge
#define NEG_INF (-1e30f)

// fused streaming kernel grid layout
#define NPART 256
#define NBLK_IN 2048
#define NBLK_OUT 4096
#define NFUSED (NPART + NBLK_IN + NBLK_OUT)

// attention dynamic smem (float units): kbuf 32*512 half = 8192 f | q 512 | p 512 | sel 32
#define SM_K    0
#define SM_Q    8192
#define SM_P    8704
#define SM_SEL  9216
#define SMEM_ATT_BYTES (9248 * 4 + 128)

// ------------------- device scratch (touched ONLY from device code) --------
__device__ __half g_in_h [(size_t)BB * NBLK * 4 * DE];   // fp16 blockified m_in
__device__ __half g_out_h[(size_t)BB * NBLK * 4 * DO];   // fp16 blockified m_out
__device__ float4 g_pval[(size_t)BB * NCOLS * NCHUNK];
__device__ float  g_pv4 [(size_t)BB * NCOLS * NCHUNK];
__device__ int4   g_pidx[(size_t)BB * NCOLS * NCHUNK];
__device__ int    g_px4 [(size_t)BB * NCOLS * NCHUNK];
__device__ int    g_sel [(size_t)BB * NCOLS * KSEL];     // asc-sorted top-32

// ---------------------------- cp.async helpers -----------------------------
__device__ __forceinline__ void cp16(void* smem_dst, const void* gmem_src) {
    unsigned sa = (unsigned)__cvta_generic_to_shared(smem_dst);
    asm volatile("cp.async.cg.shared.global [%0], [%1], 16;\n" :: "r"(sa), "l"(gmem_src));
}
__device__ __forceinline__ void cp_commit() { asm volatile("cp.async.commit_group;\n"); }
template<int N> __device__ __forceinline__ void cp_wait() {
    asm volatile("cp.async.wait_group %0;\n" :: "n"(N));
}

// ---- blockify body: [B,D,T,H,W] -> fp16 [B, n, pos=i*2+j, D] --------------
// float4 loads (8 LDG.128/thread), scalar smem transpose, half2 stores
template<int D, int NCH>
__device__ __forceinline__ void blockify_body(const float* __restrict__ src,
                                              __half* __restrict__ dst,
                                              int h, int t, int zc,
                                              float (*tile)[65]) {
    const int b  = zc / NCH;
    const int c0 = (zc % NCH) * 128;
    const int tid = threadIdx.x;

    {
        const int wq = tid & 15;            // float4 index along w
        const int cl = tid >> 4;            // 0..15
        const float* base = src
            + (size_t)b * D * (TT * HH * WW)
            + (size_t)c0 * (TT * HH * WW)
            + (size_t)t * (HH * WW)
            + (size_t)h * WW;
#pragma unroll
        for (int it = 0; it < 8; it++) {
            const int c = cl + 16 * it;
            const float4 v = *(const float4*)(base + (size_t)c * (TT * HH * WW) + 4 * wq);
            tile[c][4 * wq + 0] = v.x;
            tile[c][4 * wq + 1] = v.y;
            tile[c][4 * wq + 2] = v.z;
            tile[c][4 * wq + 3] = v.w;
        }
    }
    __syncthreads();

    const int hb = h >> 1, ii = h & 1;
    const int cp = tid & 63;             // channel pair: c = 2cp, 2cp+1
    const int mg = tid >> 6;             // 0..3
    const size_t blk_base = (size_t)b * NBLK + (size_t)t * (HREF * WREF) + (size_t)hb * WREF;
#pragma unroll
    for (int m = mg; m < 64; m += 4) {
        const int wb = m >> 1, jj = m & 1;
        const size_t o = ((blk_base + wb) * 4 + (ii * 2 + jj)) * (size_t)D + c0 + 2 * cp;
        *(__half2*)(dst + o) = __floats2half2_rn(tile[2 * cp][m], tile[2 * cp + 1][m]);
    }
}

// ---- partial body: per (column, chunk) thread; register top-5 -------------
__device__ __forceinline__ void partial_body(const float* __restrict__ qk,
                                             int jBlk, int chunk, int b) {
    const int tid = threadIdx.x;
    const int j = jBlk * 256 + tid;
    const float* col = qk + (size_t)b * NBLK * NCOLS + (size_t)chunk * CHUNK * NCOLS + j;

    float w[LSZ];
    int   x[LSZ];
#pragma unroll
    for (int e = 0; e < LSZ; e++) { w[e] = NEG_INF; x[e] = 0x7fffffff; }
    const int rbase = chunk * CHUNK;

    for (int r0 = 0; r0 < CHUNK; r0 += 16) {
        float vv[16];
#pragma unroll
        for (int u = 0; u < 16; u++) vv[u] = col[(size_t)(r0 + u) * NCOLS];
#pragma unroll
        for (int u = 0; u < 16; u++) {
            const float v = vv[u];
            if (v > w[LSZ - 1]) {              // strict > + asc scan = jax ties
                const int myi = rbase + r0 + u;
                bool bprev = true;
#pragma unroll
                for (int e = LSZ - 1; e >= 1; e--) {
                    const bool b1 = v > w[e - 1];
                    w[e] = b1 ? w[e - 1] : (bprev ? v   : w[e]);
                    x[e] = b1 ? x[e - 1] : (bprev ? myi : x[e]);
                    bprev = b1;
                }
                if (bprev) { w[0] = v; x[0] = myi; }
            }
        }
    }
    const size_t o = (size_t)(b * NCOLS + j) * NCHUNK + chunk;
    g_pval[o] = make_float4(w[0], w[1], w[2], w[3]);
    g_pv4 [o] = w[4];
    g_pidx[o] = make_int4(x[0], x[1], x[2], x[3]);
    g_px4 [o] = x[4];
}

// ---- fused streaming kernel ------------------------------------------------
__global__ void fused_stream_k(const float* __restrict__ m_in,
                               const float* __restrict__ m_out,
                               const float* __restrict__ qk) {
    __shared__ float tile[128][65];
    const int bid = blockIdx.x;
    if (bid < NPART) {
        partial_body(qk, bid & 3, (bid >> 2) & 31, bid >> 7);
    } else if (bid < NPART + NBLK_IN) {
        const int id = bid - NPART;
        blockify_body<DE, 1>(m_in, g_in_h, id & 63, (id >> 6) & 15, id >> 10, tile);
    } else {
        const int id = bid - NPART - NBLK_IN;
        blockify_body<DO, 2>(m_out, g_out_h, id & 63, (id >> 6) & 15, id >> 10, tile);
    }
}

// ---- warp sort / merge (desc, value-only) ---------------------------------
__device__ __forceinline__ float wsort_desc(float c) {
    const int lane = threadIdx.x & 31;
#pragma unroll
    for (int k = 2; k <= 32; k <<= 1)
#pragma unroll
        for (int d = k >> 1; d; d >>= 1) {
            const float o = __shfl_xor_sync(0xffffffffu, c, d);
            const bool keepmax = (((lane & d) == 0) == ((lane & k) == 0));
            c = keepmax ? fmaxf(c, o) : fminf(c, o);
        }
    return c;
}
__device__ __forceinline__ float wmerge_desc(float a, float bfull) {
    const int lane = threadIdx.x & 31;
    const float br = __shfl_sync(0xffffffffu, bfull, 31 - lane);
    float c = fmaxf(a, br);
#pragma unroll
    for (int d = 16; d >= 1; d >>= 1) {
        const float o = __shfl_xor_sync(0xffffffffu, c, d);
        c = ((lane & d) == 0) ? fmaxf(c, o) : fminf(c, o);
    }
    return c;
}
__device__ __forceinline__ int wsort_int_asc(int x) {
    const int lane = threadIdx.x & 31;
#pragma unroll
    for (int k = 2; k <= 32; k <<= 1)
#pragma unroll
        for (int d = k >> 1; d; d >>= 1) {
            const int o = __shfl_xor_sync(0xffffffffu, x, d);
            const bool keepmin = (((lane & d) == 0) == ((lane & k) == 0));
            x = keepmin ? min(x, o) : max(x, o);
        }
    return x;
}
__device__ __forceinline__ bool beats(float av, int ai, float bv, int bi) {
    return (av > bv) || (av == bv && ai < bi);
}

// ---- merge + finalize: exact top-32 per column ----------------------------
// grid (NCOLS/2, BB), block 64 (2 warps, 1 column each) — better spread
__global__ void topk_merge_k(const float* __restrict__ qk,
                             float* __restrict__ out_idx, float* __restrict__ out_val) {
    __shared__ float cand_v[2][CAPM];
    __shared__ int   cand_i[2][CAPM];
    __shared__ int   cnt[2];
    const int tid = threadIdx.x, lane = tid & 31, w = tid >> 5;
    const int col = blockIdx.x * 2 + w, b = blockIdx.y;
    const int cb = b * NCOLS + col;

    const size_t po = (size_t)cb * NCHUNK + lane;
    const float4 pv = g_pval[po];
    const float  v4 = g_pv4[po];
    const int4   pi = g_pidx[po];
    const int    i4 = g_px4[po];

    float s = wsort_desc(pv.x);
    s = wmerge_desc(s, wsort_desc(pv.y));
    s = wmerge_desc(s, wsort_desc(pv.z));
    s = wmerge_desc(s, wsort_desc(pv.w));
    s = wmerge_desc(s, wsort_desc(v4));
    const float cut = __shfl_sync(0xffffffffu, s, 31);

    if (lane == 0) cnt[w] = 0;
    __syncwarp();

    const bool flagged = (v4 >= cut);
    if (!flagged) {
        const float fv[LSZ] = {pv.x, pv.y, pv.z, pv.w, v4};
        const int   fi[LSZ] = {pi.x, pi.y, pi.z, pi.w, i4};
#pragma unroll
        for (int e = 0; e < LSZ; e++)
            if (fv[e] >= cut) {
                const int pos = atomicAdd(&cnt[w], 1);
                if (pos < CAPM) { cand_v[w][pos] = fv[e]; cand_i[w][pos] = fi[e]; }
            }
    }
    unsigned mask = __ballot_sync(0xffffffffu, flagged);
    while (mask) {                        // rare: rescan flagged chunks, MLP=16
        const int cc = __ffs(mask) - 1; mask &= mask - 1;
        const float* colp = qk + (size_t)b * NBLK * NCOLS + (size_t)(cc * CHUNK) * NCOLS + col;
        float vv[16];
#pragma unroll
        for (int u = 0; u < 16; u++)
            vv[u] = __ldg(colp + (size_t)(lane + u * 32) * NCOLS);
#pragma unroll
        for (int u = 0; u < 16; u++) {
            if (vv[u] >= cut) {
                const int pos = atomicAdd(&cnt[w], 1);
                if (pos < CAPM) { cand_v[w][pos] = vv[u]; cand_i[w][pos] = cc * CHUNK + lane + u * 32; }
            }
        }
    }
    __syncwarp();
    const int n = min(cnt[w], CAPM);
    for (int t = lane; t < CAPM; t += 32)
        if (t >= n) { cand_v[w][t] = NEG_INF; cand_i[w][t] = 0x7fffffff; }
    __syncwarp();

    for (int k = 2; k <= CAPM; k <<= 1) {
        for (int jj = k >> 1; jj > 0; jj >>= 1) {
#pragma unroll
            for (int t = lane; t < CAPM; t += 32) {
                const int ixj = t ^ jj;
                if (ixj > t) {
                    float av = cand_v[w][t], bv = cand_v[w][ixj];
                    int   ai = cand_i[w][t], bi = cand_i[w][ixj];
                    const bool desc = ((t & k) == 0);
                    const bool sw = desc ? beats(bv, bi, av, ai) : beats(av, ai, bv, bi);
                    if (sw) { cand_v[w][t] = bv; cand_v[w][ixj] = av;
                              cand_i[w][t] = bi; cand_i[w][ixj] = ai; }
                }
            }
            __syncwarp();
        }
    }

    if (lane < KK) {
        out_val[cb * KK + lane] = cand_v[w][lane];
        out_idx[cb * KK + lane] = (float)cand_i[w][lane];
    }
    const int asc = wsort_int_asc(cand_i[w][lane]);
    g_sel[(size_t)cb * KSEL + lane] = asc;
}

// ---- attention: fp16 K resident in smem; half2 channel-pair V pipeline ----
// grid (BB*NCOLS), block 256, dynamic smem ~37 KB
__global__ void __launch_bounds__(256) attention_k(
        const float* __restrict__ q_in, float* __restrict__ out) {
    extern __shared__ float sm[];
    __half* kbuf = (__half*)(sm + SM_K);   // [32][512] halves (32 KB)
    float*  q_s  = sm + SM_Q;              // [4][128]
    float*  p_s  = sm + SM_P;              // [4][128]
    int*    sel  = (int*)(sm + SM_SEL);

    const int tid = threadIdx.x;
    const int b = blockIdx.x >> 10;
    const int colq = blockIdx.x & 1023;
    const int hr = colq >> 5, wr = colq & 31;
    const int cb = b * NCOLS + colq;

    if (tid < KSEL) sel[tid] = g_sel[(size_t)cb * KSEL + tid];
    __syncthreads();

    // issue ALL 32 K-block cp.asyncs (32 KB, one commit group)
    const size_t gbase = (size_t)b * NBLK;
#pragma unroll
    for (int i = 0; i < 8; i++) {
        const int f4 = i * 256 + tid;
        const int slot = f4 >> 6, off = f4 & 63;
        cp16(kbuf + (size_t)f4 * 8,
             (const uint4*)g_in_h + (gbase + sel[slot]) * 64 + off);
    }
    cp_commit();

    // q load + pre-scale (overlaps K transfer)
    {
        const int c = tid & 127, ii = tid >> 7;
        const size_t qoff = ((size_t)(b * DE + c) * HH + (2 * hr + ii)) * WW + 2 * wr;
        const float2 qv = *(const float2*)(q_in + qoff);
        const float sc = 0.08838834764831845f;     // 1/sqrt(128)
        q_s[(ii * 2 + 0) * 128 + c] = qv.x * sc;
        q_s[(ii * 2 + 1) * 128 + c] = qv.y * sc;
    }

    // V prefetch (depth 8) issued BEFORE QK.
    // Thread (hw, qh): channels {2hw, 2hw+1}, queries {2qh, 2qh+1}.
    const int hw = tid & 127, qh = tid >> 7;
    unsigned vrr[8][4];
#pragma unroll
    for (int s = 0; s < 8; s++) {
        const __half* src = g_out_h + (gbase + sel[s]) * 1024 + 2 * hw;
#pragma unroll
        for (int pos = 0; pos < 4; pos++)
            vrr[s][pos] = __ldg((const unsigned*)(src + pos * 256));
    }

    cp_wait<0>();
    __syncthreads();

    // QK: sync-free; q fp32 in registers, K half2 from smem
    const int grp = tid >> 4, sub = tid & 15;
    const int ql = grp >> 2, pl = grp & 3;
    float qr[8];
#pragma unroll
    for (int k = 0; k < 4; k++) {
        qr[2 * k]     = q_s[ql * 128 + 2 * (sub + 16 * k)];
        qr[2 * k + 1] = q_s[ql * 128 + 2 * (sub + 16 * k) + 1];
    }
#pragma unroll 4
    for (int s = 0; s < KSEL; s++) {
        const __half2* kv = (const __half2*)kbuf + s * 256 + pl * 64;
        float part = 0.f;
#pragma unroll
        for (int k = 0; k < 4; k++) {
            const float2 kf = __half22float2(kv[sub + 16 * k]);
            part += qr[2 * k] * kf.x + qr[2 * k + 1] * kf.y;
        }
        part += __shfl_xor_sync(0xffffffffu, part, 8);
        part += __shfl_xor_sync(0xffffffffu, part, 4);
        part += __shfl_xor_sync(0xffffffffu, part, 2);
        part += __shfl_xor_sync(0xffffffffu, part, 1);
        if (sub == 0) p_s[ql * 128 + s * 4 + pl] = part;
    }
    __syncthreads();

    // softmax over 128 keys; one warp per query
    {
        const int w = tid >> 5, lane = tid & 31;
        if (w < 4) {
            float x0 = p_s[w * 128 + lane],      x1 = p_s[w * 128 + lane + 32];
            float x2 = p_s[w * 128 + lane + 64], x3 = p_s[w * 128 + lane + 96];
            float m = fmaxf(fmaxf(x0, x1), fmaxf(x2, x3));
#pragma unroll
            for (int o = 16; o; o >>= 1) m = fmaxf(m, __shfl_xor_sync(0xffffffffu, m, o));
            float e0 = __expf(x0 - m), e1 = __expf(x1 - m);
            float e2 = __expf(x2 - m), e3 = __expf(x3 - m);
            float ssum = e0 + e1 + e2 + e3;
#pragma unroll
            for (int o = 16; o; o >>= 1) ssum += __shfl_xor_sync(0xffffffffu, ssum, o);
            const float inv = __fdividef(1.f, ssum);
            p_s[w * 128 + lane]      = e0 * inv; p_s[w * 128 + lane + 32] = e1 * inv;
            p_s[w * 128 + lane + 64] = e2 * inv; p_s[w * 128 + lane + 96] = e3 * inv;
        }
    }
    __syncthreads();

    // PV: half2 channel-pair register pipeline, depth 8, zero syncs
    float a00 = 0.f, a01 = 0.f, a10 = 0.f, a11 = 0.f;
    const float* pq0 = p_s + (2 * qh + 0) * 128;
    const float* pq1 = p_s + (2 * qh + 1) * 128;
#pragma unroll 8
    for (int s = 0; s < KSEL; s++) {
        const int rs = s & 7;
        const float4 pA = *(const float4*)(pq0 + s * 4);
        const float4 pB = *(const float4*)(pq1 + s * 4);
        float2 v;
        v = __half22float2(*(const __half2*)&vrr[rs][0]);
        a00 += v.x * pA.x; a01 += v.y * pA.x; a10 += v.x * pB.x; a11 += v.y * pB.x;
        v = __half22float2(*(const __half2*)&vrr[rs][1]);
        a00 += v.x * pA.y; a01 += v.y * pA.y; a10 += v.x * pB.y; a11 += v.y * pB.y;
        v = __half22float2(*(const __half2*)&vrr[rs][2]);
        a00 += v.x * pA.z; a01 += v.y * pA.z; a10 += v.x * pB.z; a11 += v.y * pB.z;
        v = __half22float2(*(const __half2*)&vrr[rs][3]);
        a00 += v.x * pA.w; a01 += v.y * pA.w; a10 += v.x * pB.w; a11 += v.y * pB.w;
        if (s + 8 < KSEL) {
            const __half* src = g_out_h + (gbase + sel[s + 8]) * 1024 + 2 * hw;
#pragma unroll
            for (int pos = 0; pos < 4; pos++)
                vrr[rs][pos] = __ldg((const unsigned*)(src + pos * 256));
        }
    }

    // outputs: channel 2hw: queries (2qh -> col 2wr), (2qh+1 -> col 2wr+1), row 2hr+qh
    size_t ob = ((size_t)(b * DO + 2 * hw) * HH + 2 * hr + qh) * WW + 2 * wr;
    *(float2*)(out + ob) = make_float2(a00, a10);
    ob += (size_t)HH * WW;
    *(float2*)(out + ob) = make_float2(a01, a11);
}

// ---------------------------------------------------------------------------
extern "C" void kernel_launch(void* const* d_in, const int* in_sizes, int n_in,
                              void* d_out, int out_size) {
    const float* m_in   = (const float*)d_in[0];
    const float* m_out  = (const float*)d_in[1];
    const float* q_in   = (const float*)d_in[2];
    const float* qk_ref = (const float*)d_in[3];

    float* out_mem = (float*)d_out;
    float* out_idx = out_mem + (size_t)BB * DO * HH * WW;
    float* out_val = out_idx + (size_t)BB * NCOLS * KK;

    // fused: topk partial + blockify m_in + blockify m_out (one launch)
    fused_stream_k<<<NFUSED, 256>>>(m_in, m_out, qk_ref);
    // merge + finalize selection (64-thread CTAs for spread)
    {
        dim3 gm(NCOLS / 2, BB);
        topk_merge_k<<<gm, 64>>>(qk_ref, out_idx, out_val);
    }
    // attention
    cudaFuncSetAttribute(attention_k, cudaFuncAttributeMaxDynamicSharedMemorySize, SMEM_ATT_BYTES);
    attention_k<<<BB * NCOLS, 256, SMEM_ATT_BYTES>>>(q_in, out_mem);
}

// round 17
// speedup vs baseline: 1.1466x; 1.0216x over previous
#include <cuda_runtime.h>
#include <cuda_fp16.h>
#include <cstdint>

#define BB 2
#define DE 128
#define DO 256
#define TT 16
#define HH 64
#define WW 64
#define HREF 32
#define WREF 32
#define NBLK 16384   // TT * HREF * WREF
#define NCOLS 1024   // HREF * WREF
#define KSEL 32
#define KK 8
#define NCHUNK 32
#define CHUNK 512    // NBLK / NCHUNK
#define LSZ 5        // per-chunk candidate list depth
#define CAPM 64      // per-column candidate cap in merge
#define NEG_INF (-1e30f)

// fused streaming kernel grid layout
#define NPART 256
#define NBLK_IN 2048
#define NBLK_OUT 4096
#define NFUSED (NPART + NBLK_IN + NBLK_OUT)

// attention dynamic smem (float units): kbuf 32*512 half = 8192 f | q 512 | p 512 | sel 32
#define SM_K    0
#define SM_Q    8192
#define SM_P    8704
#define SM_SEL  9216
#define SMEM_ATT_BYTES (9248 * 4 + 128)

// ------------------- device scratch (touched ONLY from device code) --------
__device__ __half g_in_h [(size_t)BB * NBLK * 4 * DE];   // fp16 blockified m_in
__device__ __half g_out_h[(size_t)BB * NBLK * 4 * DO];   // fp16 blockified m_out
__device__ float4 g_pval[(size_t)BB * NCOLS * NCHUNK];
__device__ float  g_pv4 [(size_t)BB * NCOLS * NCHUNK];
__device__ int4   g_pidx[(size_t)BB * NCOLS * NCHUNK];
__device__ int    g_px4 [(size_t)BB * NCOLS * NCHUNK];
__device__ int    g_sel [(size_t)BB * NCOLS * KSEL];     // asc-sorted top-32

// ---------------------------- cp.async helpers -----------------------------
__device__ __forceinline__ void cp16(void* smem_dst, const void* gmem_src) {
    unsigned sa = (unsigned)__cvta_generic_to_shared(smem_dst);
    asm volatile("cp.async.cg.shared.global [%0], [%1], 16;\n" :: "r"(sa), "l"(gmem_src));
}
__device__ __forceinline__ void cp_commit() { asm volatile("cp.async.commit_group;\n"); }
template<int N> __device__ __forceinline__ void cp_wait() {
    asm volatile("cp.async.wait_group %0;\n" :: "n"(N));
}

// ---- blockify body: [B,D,T,H,W] -> fp16 [B, n, pos=i*2+j, D] --------------
// float4 loads (8 LDG.128/thread), scalar smem transpose, half2 stores
template<int D, int NCH>
__device__ __forceinline__ void blockify_body(const float* __restrict__ src,
                                              __half* __restrict__ dst,
                                              int h, int t, int zc,
                                              float (*tile)[65]) {
    const int b  = zc / NCH;
    const int c0 = (zc % NCH) * 128;
    const int tid = threadIdx.x;

    {
        const int wq = tid & 15;            // float4 index along w
        const int cl = tid >> 4;            // 0..15
        const float* base = src
            + (size_t)b * D * (TT * HH * WW)
            + (size_t)c0 * (TT * HH * WW)
            + (size_t)t * (HH * WW)
            + (size_t)h * WW;
#pragma unroll
        for (int it = 0; it < 8; it++) {
            const int c = cl + 16 * it;
            const float4 v = *(const float4*)(base + (size_t)c * (TT * HH * WW) + 4 * wq);
            tile[c][4 * wq + 0] = v.x;
            tile[c][4 * wq + 1] = v.y;
            tile[c][4 * wq + 2] = v.z;
            tile[c][4 * wq + 3] = v.w;
        }
    }
    __syncthreads();

    const int hb = h >> 1, ii = h & 1;
    const int cp = tid & 63;             // channel pair: c = 2cp, 2cp+1
    const int mg = tid >> 6;             // 0..3
    const size_t blk_base = (size_t)b * NBLK + (size_t)t * (HREF * WREF) + (size_t)hb * WREF;
#pragma unroll
    for (int m = mg; m < 64; m += 4) {
        const int wb = m >> 1, jj = m & 1;
        const size_t o = ((blk_base + wb) * 4 + (ii * 2 + jj)) * (size_t)D + c0 + 2 * cp;
        *(__half2*)(dst + o) = __floats2half2_rn(tile[2 * cp][m], tile[2 * cp + 1][m]);
    }
}

// ---- partial body: per (column, chunk) thread; register top-5 -------------
__device__ __forceinline__ void partial_body(const float* __restrict__ qk,
                                             int jBlk, int chunk, int b) {
    const int tid = threadIdx.x;
    const int j = jBlk * 256 + tid;
    const float* col = qk + (size_t)b * NBLK * NCOLS + (size_t)chunk * CHUNK * NCOLS + j;

    float w[LSZ];
    int   x[LSZ];
#pragma unroll
    for (int e = 0; e < LSZ; e++) { w[e] = NEG_INF; x[e] = 0x7fffffff; }
    const int rbase = chunk * CHUNK;

    for (int r0 = 0; r0 < CHUNK; r0 += 16) {
        float vv[16];
#pragma unroll
        for (int u = 0; u < 16; u++) vv[u] = col[(size_t)(r0 + u) * NCOLS];
#pragma unroll
        for (int u = 0; u < 16; u++) {
            const float v = vv[u];
            if (v > w[LSZ - 1]) {              // strict > + asc scan = jax ties
                const int myi = rbase + r0 + u;
                bool bprev = true;
#pragma unroll
                for (int e = LSZ - 1; e >= 1; e--) {
                    const bool b1 = v > w[e - 1];
                    w[e] = b1 ? w[e - 1] : (bprev ? v   : w[e]);
                    x[e] = b1 ? x[e - 1] : (bprev ? myi : x[e]);
                    bprev = b1;
                }
                if (bprev) { w[0] = v; x[0] = myi; }
            }
        }
    }
    const size_t o = (size_t)(b * NCOLS + j) * NCHUNK + chunk;
    g_pval[o] = make_float4(w[0], w[1], w[2], w[3]);
    g_pv4 [o] = w[4];
    g_pidx[o] = make_int4(x[0], x[1], x[2], x[3]);
    g_px4 [o] = x[4];
}

// ---- fused streaming kernel ------------------------------------------------
__global__ void fused_stream_k(const float* __restrict__ m_in,
                               const float* __restrict__ m_out,
                               const float* __restrict__ qk) {
    __shared__ float tile[128][65];
    const int bid = blockIdx.x;
    if (bid < NPART) {
        partial_body(qk, bid & 3, (bid >> 2) & 31, bid >> 7);
    } else if (bid < NPART + NBLK_IN) {
        const int id = bid - NPART;
        blockify_body<DE, 1>(m_in, g_in_h, id & 63, (id >> 6) & 15, id >> 10, tile);
    } else {
        const int id = bid - NPART - NBLK_IN;
        blockify_body<DO, 2>(m_out, g_out_h, id & 63, (id >> 6) & 15, id >> 10, tile);
    }
}

// ---- warp sort / merge (desc, value-only) ---------------------------------
__device__ __forceinline__ float wsort_desc(float c) {
    const int lane = threadIdx.x & 31;
#pragma unroll
    for (int k = 2; k <= 32; k <<= 1)
#pragma unroll
        for (int d = k >> 1; d; d >>= 1) {
            const float o = __shfl_xor_sync(0xffffffffu, c, d);
            const bool keepmax = (((lane & d) == 0) == ((lane & k) == 0));
            c = keepmax ? fmaxf(c, o) : fminf(c, o);
        }
    return c;
}
__device__ __forceinline__ float wmerge_desc(float a, float bfull) {
    const int lane = threadIdx.x & 31;
    const float br = __shfl_sync(0xffffffffu, bfull, 31 - lane);
    float c = fmaxf(a, br);
#pragma unroll
    for (int d = 16; d >= 1; d >>= 1) {
        const float o = __shfl_xor_sync(0xffffffffu, c, d);
        c = ((lane & d) == 0) ? fmaxf(c, o) : fminf(c, o);
    }
    return c;
}
__device__ __forceinline__ int wsort_int_asc(int x) {
    const int lane = threadIdx.x & 31;
#pragma unroll
    for (int k = 2; k <= 32; k <<= 1)
#pragma unroll
        for (int d = k >> 1; d; d >>= 1) {
            const int o = __shfl_xor_sync(0xffffffffu, x, d);
            const bool keepmin = (((lane & d) == 0) == ((lane & k) == 0));
            x = keepmin ? min(x, o) : max(x, o);
        }
    return x;
}
__device__ __forceinline__ bool beats(float av, int ai, float bv, int bi) {
    return (av > bv) || (av == bv && ai < bi);
}

// ---- merge + finalize: exact top-32 per column ----------------------------
// grid (NCOLS/2, BB), block 64 (2 warps, 1 column each)
__global__ void topk_merge_k(const float* __restrict__ qk,
                             float* __restrict__ out_idx, float* __restrict__ out_val) {
    __shared__ float cand_v[2][CAPM];
    __shared__ int   cand_i[2][CAPM];
    __shared__ int   cnt[2];
    const int tid = threadIdx.x, lane = tid & 31, w = tid >> 5;
    const int col = blockIdx.x * 2 + w, b = blockIdx.y;
    const int cb = b * NCOLS + col;

    const size_t po = (size_t)cb * NCHUNK + lane;
    const float4 pv = g_pval[po];
    const float  v4 = g_pv4[po];
    const int4   pi = g_pidx[po];
    const int    i4 = g_px4[po];

    float s = wsort_desc(pv.x);
    s = wmerge_desc(s, wsort_desc(pv.y));
    s = wmerge_desc(s, wsort_desc(pv.z));
    s = wmerge_desc(s, wsort_desc(pv.w));
    s = wmerge_desc(s, wsort_desc(v4));
    const float cut = __shfl_sync(0xffffffffu, s, 31);

    if (lane == 0) cnt[w] = 0;
    __syncwarp();

    const bool flagged = (v4 >= cut);
    if (!flagged) {
        const float fv[LSZ] = {pv.x, pv.y, pv.z, pv.w, v4};
        const int   fi[LSZ] = {pi.x, pi.y, pi.z, pi.w, i4};
#pragma unroll
        for (int e = 0; e < LSZ; e++)
            if (fv[e] >= cut) {
                const int pos = atomicAdd(&cnt[w], 1);
                if (pos < CAPM) { cand_v[w][pos] = fv[e]; cand_i[w][pos] = fi[e]; }
            }
    }
    unsigned mask = __ballot_sync(0xffffffffu, flagged);
    while (mask) {                        // rare: rescan flagged chunks, MLP=16
        const int cc = __ffs(mask) - 1; mask &= mask - 1;
        const float* colp = qk + (size_t)b * NBLK * NCOLS + (size_t)(cc * CHUNK) * NCOLS + col;
        float vv[16];
#pragma unroll
        for (int u = 0; u < 16; u++)
            vv[u] = __ldg(colp + (size_t)(lane + u * 32) * NCOLS);
#pragma unroll
        for (int u = 0; u < 16; u++) {
            if (vv[u] >= cut) {
                const int pos = atomicAdd(&cnt[w], 1);
                if (pos < CAPM) { cand_v[w][pos] = vv[u]; cand_i[w][pos] = cc * CHUNK + lane + u * 32; }
            }
        }
    }
    __syncwarp();
    const int n = min(cnt[w], CAPM);
    for (int t = lane; t < CAPM; t += 32)
        if (t >= n) { cand_v[w][t] = NEG_INF; cand_i[w][t] = 0x7fffffff; }
    __syncwarp();

    for (int k = 2; k <= CAPM; k <<= 1) {
        for (int jj = k >> 1; jj > 0; jj >>= 1) {
#pragma unroll
            for (int t = lane; t < CAPM; t += 32) {
                const int ixj = t ^ jj;
                if (ixj > t) {
                    float av = cand_v[w][t], bv = cand_v[w][ixj];
                    int   ai = cand_i[w][t], bi = cand_i[w][ixj];
                    const bool desc = ((t & k) == 0);
                    const bool sw = desc ? beats(bv, bi, av, ai) : beats(av, ai, bv, bi);
                    if (sw) { cand_v[w][t] = bv; cand_v[w][ixj] = av;
                              cand_i[w][t] = bi; cand_i[w][ixj] = ai; }
                }
            }
            __syncwarp();
        }
    }

    if (lane < KK) {
        out_val[cb * KK + lane] = cand_v[w][lane];
        out_idx[cb * KK + lane] = (float)cand_i[w][lane];
    }
    const int asc = wsort_int_asc(cand_i[w][lane]);
    g_sel[(size_t)cb * KSEL + lane] = asc;
}

// ---- attention: fp16 K resident; half2 V pipeline; 5 CTAs/SM --------------
// grid (BB*NCOLS), block 256, dynamic smem ~37 KB
__global__ void __launch_bounds__(256, 5) attention_k(
        const float* __restrict__ q_in, float* __restrict__ out) {
    extern __shared__ float sm[];
    __half* kbuf = (__half*)(sm + SM_K);   // [32][512] halves (32 KB)
    float*  q_s  = sm + SM_Q;              // [4][128]
    float*  p_s  = sm + SM_P;              // [4][128]
    int*    sel  = (int*)(sm + SM_SEL);

    const int tid = threadIdx.x;
    const int b = blockIdx.x >> 10;
    const int colq = blockIdx.x & 1023;
    const int hr = colq >> 5, wr = colq & 31;
    const int cb = b * NCOLS + colq;

    if (tid < KSEL) sel[tid] = g_sel[(size_t)cb * KSEL + tid];
    __syncthreads();

    // issue ALL 32 K-block cp.asyncs (32 KB, one commit group)
    const size_t gbase = (size_t)b * NBLK;
#pragma unroll
    for (int i = 0; i < 8; i++) {
        const int f4 = i * 256 + tid;
        const int slot = f4 >> 6, off = f4 & 63;
        cp16(kbuf + (size_t)f4 * 8,
             (const uint4*)g_in_h + (gbase + sel[slot]) * 64 + off);
    }
    cp_commit();

    // q load + pre-scale (overlaps K transfer)
    {
        const int c = tid & 127, ii = tid >> 7;
        const size_t qoff = ((size_t)(b * DE + c) * HH + (2 * hr + ii)) * WW + 2 * wr;
        const float2 qv = *(const float2*)(q_in + qoff);
        const float sc = 0.08838834764831845f;     // 1/sqrt(128)
        q_s[(ii * 2 + 0) * 128 + c] = qv.x * sc;
        q_s[(ii * 2 + 1) * 128 + c] = qv.y * sc;
    }

    // V prefetch (depth 4) issued BEFORE QK; cross-warp overlap covers rest
    const int hw = tid & 127, qh = tid >> 7;
    unsigned vrr[4][4];
#pragma unroll
    for (int s = 0; s < 4; s++) {
        const __half* src = g_out_h + (gbase + sel[s]) * 1024 + 2 * hw;
#pragma unroll
        for (int pos = 0; pos < 4; pos++)
            vrr[s][pos] = __ldg((const unsigned*)(src + pos * 256));
    }

    cp_wait<0>();
    __syncthreads();

    // QK: sync-free; q fp32 in registers, K half2 from smem
    const int grp = tid >> 4, sub = tid & 15;
    const int ql = grp >> 2, pl = grp & 3;
    float qr[8];
#pragma unroll
    for (int k = 0; k < 4; k++) {
        qr[2 * k]     = q_s[ql * 128 + 2 * (sub + 16 * k)];
        qr[2 * k + 1] = q_s[ql * 128 + 2 * (sub + 16 * k) + 1];
    }
#pragma unroll 4
    for (int s = 0; s < KSEL; s++) {
        const __half2* kv = (const __half2*)kbuf + s * 256 + pl * 64;
        float part = 0.f;
#pragma unroll
        for (int k = 0; k < 4; k++) {
            const float2 kf = __half22float2(kv[sub + 16 * k]);
            part += qr[2 * k] * kf.x + qr[2 * k + 1] * kf.y;
        }
        part += __shfl_xor_sync(0xffffffffu, part, 8);
        part += __shfl_xor_sync(0xffffffffu, part, 4);
        part += __shfl_xor_sync(0xffffffffu, part, 2);
        part += __shfl_xor_sync(0xffffffffu, part, 1);
        if (sub == 0) p_s[ql * 128 + s * 4 + pl] = part;
    }
    __syncthreads();

    // softmax over 128 keys; one warp per query
    {
        const int w = tid >> 5, lane = tid & 31;
        if (w < 4) {
            float x0 = p_s[w * 128 + lane],      x1 = p_s[w * 128 + lane + 32];
            float x2 = p_s[w * 128 + lane + 64], x3 = p_s[w * 128 + lane + 96];
            float m = fmaxf(fmaxf(x0, x1), fmaxf(x2, x3));
#pragma unroll
            for (int o = 16; o; o >>= 1) m = fmaxf(m, __shfl_xor_sync(0xffffffffu, m, o));
            float e0 = __expf(x0 - m), e1 = __expf(x1 - m);
            float e2 = __expf(x2 - m), e3 = __expf(x3 - m);
            float ssum = e0 + e1 + e2 + e3;
#pragma unroll
            for (int o = 16; o; o >>= 1) ssum += __shfl_xor_sync(0xffffffffu, ssum, o);
            const float inv = __fdividef(1.f, ssum);
            p_s[w * 128 + lane]      = e0 * inv; p_s[w * 128 + lane + 32] = e1 * inv;
            p_s[w * 128 + lane + 64] = e2 * inv; p_s[w * 128 + lane + 96] = e3 * inv;
        }
    }
    __syncthreads();

    // PV: half2 channel-pair register pipeline, depth 4, zero syncs
    float a00 = 0.f, a01 = 0.f, a10 = 0.f, a11 = 0.f;
    const float* pq0 = p_s + (2 * qh + 0) * 128;
    const float* pq1 = p_s + (2 * qh + 1) * 128;
#pragma unroll 4
    for (int s = 0; s < KSEL; s++) {
        const int rs = s & 3;
        const float4 pA = *(const float4*)(pq0 + s * 4);
        const float4 pB = *(const float4*)(pq1 + s * 4);
        float2 v;
        v = __half22float2(*(const __half2*)&vrr[rs][0]);
        a00 += v.x * pA.x; a01 += v.y * pA.x; a10 += v.x * pB.x; a11 += v.y * pB.x;
        v = __half22float2(*(const __half2*)&vrr[rs][1]);
        a00 += v.x * pA.y; a01 += v.y * pA.y; a10 += v.x * pB.y; a11 += v.y * pB.y;
        v = __half22float2(*(const __half2*)&vrr[rs][2]);
        a00 += v.x * pA.z; a01 += v.y * pA.z; a10 += v.x * pB.z; a11 += v.y * pB.z;
        v = __half22float2(*(const __half2*)&vrr[rs][3]);
        a00 += v.x * pA.w; a01 += v.y * pA.w; a10 += v.x * pB.w; a11 += v.y * pB.w;
        if (s + 4 < KSEL) {
            const __half* src = g_out_h + (gbase + sel[s + 4]) * 1024 + 2 * hw;
#pragma unroll
            for (int pos = 0; pos < 4; pos++)
                vrr[rs][pos] = __ldg((const unsigned*)(src + pos * 256));
        }
    }

    // outputs: channel 2hw: queries (2qh -> col 2wr), (2qh+1 -> col 2wr+1), row 2hr+qh
    size_t ob = ((size_t)(b * DO + 2 * hw) * HH + 2 * hr + qh) * WW + 2 * wr;
    *(float2*)(out + ob) = make_float2(a00, a10);
    ob += (size_t)HH * WW;
    *(float2*)(out + ob) = make_float2(a01, a11);
}

// ---------------------------------------------------------------------------
extern "C" void kernel_launch(void* const* d_in, const int* in_sizes, int n_in,
                              void* d_out, int out_size) {
    const float* m_in   = (const float*)d_in[0];
    const float* m_out  = (const float*)d_in[1];
    const float* q_in   = (const float*)d_in[2];
    const float* qk_ref = (const float*)d_in[3];

    float* out_mem = (float*)d_out;
    float* out_idx = out_mem + (size_t)BB * DO * HH * WW;
    float* out_val = out_idx + (size_t)BB * NCOLS * KK;

    // fused: topk partial + blockify m_in + blockify m_out (one launch)
    fused_stream_k<<<NFUSED, 256>>>(m_in, m_out, qk_ref);
    // merge + finalize selection (64-thread CTAs for spread)
    {
        dim3 gm(NCOLS / 2, BB);
        topk_merge_k<<<gm, 64>>>(qk_ref, out_idx, out_val);
    }
    // attention
    cudaFuncSetAttribute(attention_k, cudaFuncAttributeMaxDynamicSharedMemorySize, SMEM_ATT_BYTES);
    attention_k<<<BB * NCOLS, 256, SMEM_ATT_BYTES>>>(q_in, out_mem);
}